// round 11
// baseline (speedup 1.0000x reference)
#include <cuda_runtime.h>
#include <cstdint>
#include <math.h>

#define N_NODES_MAX 100000
#define HID 128
#define NF 128
#define NG 50

__device__ float g_x[(size_t)N_NODES_MAX * HID];
__device__ float g_agg[(size_t)N_NODES_MAX * HID];

__device__ __forceinline__ float sspf(float v) {
    float sp = (v > 20.0f) ? v : __logf(1.0f + __expf(v));
    return sp - 0.69314718056f;
}

__device__ __forceinline__ uint32_t f2tf(float f) {
    uint32_t u;
    asm("cvt.rna.tf32.f32 %0, %1;" : "=r"(u) : "f"(f));
    return u;
}

// D += A@B, m16n8k8 tf32, fp32 accumulate (baseline PTX)
__device__ __forceinline__ void mma8(float* c, const uint32_t* a, const uint32_t* b) {
    asm volatile(
        "mma.sync.aligned.m16n8k8.row.col.f32.tf32.tf32.f32 "
        "{%0,%1,%2,%3}, {%4,%5,%6,%7}, {%8,%9}, {%0,%1,%2,%3};"
        : "+f"(c[0]), "+f"(c[1]), "+f"(c[2]), "+f"(c[3])
        : "r"(a[0]), "r"(a[1]), "r"(a[2]), "r"(a[3]), "r"(b[0]), "r"(b[1]));
}

__device__ __forceinline__ void red4(float* p, float a, float b, float c, float d) {
    asm volatile("red.global.add.v4.f32 [%0], {%1, %2, %3, %4};"
                 :: "l"(p), "f"(a), "f"(b), "f"(c), "f"(d) : "memory");
}

// ------------------- Edge MLP (tf32 mma.sync, 16 warps) -------------------
// Tile = 128 edges. 16 warps x 8 output filters each. Low regs (~110) so 4
// warps/SMSP actually pipeline. Scalar LDS.32 fragment loads with verified
// conflict-free strides (addr mod 32 distinct over all 32 lanes):
//   AS=60:  60*16*mt=0, 60*gi mod 32 = 28*gi in {0,4,..,28} distinct, +ci 0..3
//   HS=140: 140*gi mod 32 = 12*gi in {0,4,..,28} distinct, +ci 0..3
#define AS 60
#define HS 140

#define EO_ATTR 0
#define EO_HID  (128 * AS)                 // 7680
#define EO_ROWS (EO_HID + 128 * HS)        // 25600
#define EO_COLS (EO_ROWS + 128)
#define EO_CW   (EO_COLS + 128)
#define EO_D    (EO_CW + 128)
#define EO_B1   (EO_D + 128)
#define EO_B2   (EO_B1 + 128)
#define E_SMEM_WORDS (EO_B2 + 128)         // 26368 words = 105472 B

__global__ __launch_bounds__(512, 1) void edge_mma_kernel(
    const float* __restrict__ pos, const int* __restrict__ ei,
    const float* __restrict__ w1, const float* __restrict__ b1,
    const float* __restrict__ w2, const float* __restrict__ b2,
    const float* __restrict__ x, float* __restrict__ agg, int E)
{
    extern __shared__ float s[];
    uint32_t* attrT = (uint32_t*)(s + EO_ATTR);   // tf32 bits
    uint32_t* hidT  = (uint32_t*)(s + EO_HID);    // tf32 bits
    int*   rowsS = (int*)(s + EO_ROWS);
    int*   colsS = (int*)(s + EO_COLS);
    float* cwS   = s + EO_CW;
    float* dS    = s + EO_D;
    float* b1sS  = s + EO_B1;
    float* b2sS  = s + EO_B2;

    const int tid = threadIdx.x;
    const int wid = tid >> 5, lane = tid & 31;
    const int gi = lane >> 2, ci = lane & 3;
    const int nbase = wid * 8;                 // 16 warps x 8 filters

    // Persistent B fragments (tf32) in registers: one n8 column block per warp.
    uint32_t b1u[7][2], b2u[16][2];
    {
        int n = nbase + gi;
        #pragma unroll
        for (int kt = 0; kt < 7; kt++) {
            int k0 = kt * 8 + ci;
            b1u[kt][0] = f2tf((k0 < NG) ? w1[k0 * 128 + n] : 0.f);
            b1u[kt][1] = f2tf((k0 + 4 < NG) ? w1[(k0 + 4) * 128 + n] : 0.f);
        }
        #pragma unroll
        for (int kt = 0; kt < 16; kt++) {
            int k0 = kt * 8 + ci;
            b2u[kt][0] = f2tf(w2[k0 * 128 + n]);
            b2u[kt][1] = f2tf(w2[(k0 + 4) * 128 + n]);
        }
    }
    if (tid < 128) { b1sS[tid] = b1[tid]; b2sS[tid] = b2[tid]; }
    __syncthreads();

    float b1v[2], b2v[2];
    {
        int n0 = nbase + 2 * ci;
        b1v[0] = b1sS[n0]; b1v[1] = b1sS[n0 + 1];
        b2v[0] = b2sS[n0]; b2v[1] = b2sS[n0 + 1];
    }

    const float step  = 10.0f / 49.0f;
    const float coeff = -0.5f / (step * step);

    for (int base = blockIdx.x * 128; base < E; base += gridDim.x * 128) {
        // ---- per-edge geometry ----
        if (tid < 128) {
            int e = base + tid;
            if (e < E) {
                int r = ei[e], c = ei[E + e];
                rowsS[tid] = r; colsS[tid] = c;
                float dx = pos[3 * r + 0] - pos[3 * c + 0];
                float dy = pos[3 * r + 1] - pos[3 * c + 1];
                float dz = pos[3 * r + 2] - pos[3 * c + 2];
                float d = sqrtf(dx * dx + dy * dy + dz * dz);
                dS[tid] = d;
                cwS[tid] = 0.5f * (__cosf(d * 0.314159265358979f) + 1.0f);
            } else {
                rowsS[tid] = 0; colsS[tid] = 0; dS[tid] = 0.f; cwS[tid] = 0.f;
            }
        }
        __syncthreads();

        // ---- Gaussian smearing -> tf32 bits, attr[128][56] (cols >= 50 zero) ----
        {
            int e = tid >> 2, q = tid & 3;     // 4 threads per edge, 14 cols each
            float d = dS[e];
            #pragma unroll
            for (int j = 0; j < 14; j++) {
                int k = q * 14 + j;
                float diff = d - (float)k * step;
                attrT[e * AS + k] = f2tf((k < NG) ? __expf(coeff * diff * diff) : 0.f);
            }
        }
        __syncthreads();

        float acc[8][4];
        #pragma unroll
        for (int mt = 0; mt < 8; mt++)
            #pragma unroll
            for (int q = 0; q < 4; q++) acc[mt][q] = 0.f;

        // ---- Layer 1: [128,56] @ [56,8] per warp ----
        #pragma unroll
        for (int kt = 0; kt < 7; kt++) {
            #pragma unroll
            for (int mt = 0; mt < 8; mt++) {
                int r = mt * 16 + gi;
                uint32_t a[4];
                a[0] = attrT[r * AS + kt * 8 + ci];
                a[1] = attrT[(r + 8) * AS + kt * 8 + ci];
                a[2] = attrT[r * AS + kt * 8 + ci + 4];
                a[3] = attrT[(r + 8) * AS + kt * 8 + ci + 4];
                mma8(acc[mt], a, b1u[kt]);
            }
        }

        // ---- bias + ssp -> hid tf32 bits (only our 8 columns) ----
        #pragma unroll
        for (int mt = 0; mt < 8; mt++) {
            int r = mt * 16 + gi;
            int n0 = nbase + 2 * ci;
            uint2 v0, v1;
            v0.x = f2tf(sspf(acc[mt][0] + b1v[0]));
            v0.y = f2tf(sspf(acc[mt][1] + b1v[1]));
            v1.x = f2tf(sspf(acc[mt][2] + b1v[0]));
            v1.y = f2tf(sspf(acc[mt][3] + b1v[1]));
            *(uint2*)&hidT[r * HS + n0] = v0;
            *(uint2*)&hidT[(r + 8) * HS + n0] = v1;
        }
        __syncthreads();

        #pragma unroll
        for (int mt = 0; mt < 8; mt++)
            #pragma unroll
            for (int q = 0; q < 4; q++) acc[mt][q] = 0.f;

        // ---- Layer 2: [128,128] @ [128,8] per warp ----
        #pragma unroll
        for (int kt = 0; kt < 16; kt++) {
            #pragma unroll
            for (int mt = 0; mt < 8; mt++) {
                int r = mt * 16 + gi;
                uint32_t a[4];
                a[0] = hidT[r * HS + kt * 8 + ci];
                a[1] = hidT[(r + 8) * HS + kt * 8 + ci];
                a[2] = hidT[r * HS + kt * 8 + ci + 4];
                a[3] = hidT[(r + 8) * HS + kt * 8 + ci + 4];
                mma8(acc[mt], a, b2u[kt]);
            }
        }

        // ---- epilogue: bias, cutoff, pair-shuffle -> float4 gather + red.v4 ----
        {
            const int odd = ci & 1;
            const int cb = nbase + 4 * (ci >> 1);
            #pragma unroll
            for (int mt = 0; mt < 8; mt++) {
                int r0 = mt * 16 + gi, r1 = r0 + 8;
                float cw0 = cwS[r0], cw1 = cwS[r1];
                int mr = odd ? r1 : r0;
                int gr = rowsS[mr], gc = colsS[mr];
                float wa = (acc[mt][0] + b2v[0]) * cw0;
                float wb = (acc[mt][1] + b2v[1]) * cw0;
                float wc = (acc[mt][2] + b2v[0]) * cw1;
                float wd = (acc[mt][3] + b2v[1]) * cw1;
                // lane pair (ci, ci^1): even lane keeps row r0, odd keeps r1.
                float sx = odd ? wa : wc;
                float sy = odd ? wb : wd;
                float rx = __shfl_xor_sync(0xffffffffu, sx, 1);
                float ry = __shfl_xor_sync(0xffffffffu, sy, 1);
                float v0 = odd ? rx : wa;
                float v1 = odd ? ry : wb;
                float v2 = odd ? wc : rx;
                float v3 = odd ? wd : ry;
                float4 xv = *(const float4*)&x[(size_t)gc * 128 + cb];
                red4(&agg[(size_t)gr * 128 + cb],
                     v0 * xv.x, v1 * xv.y, v2 * xv.z, v3 * xv.w);
            }
        }
        __syncthreads();
    }
}

// ------------------- Node GEMM (fp32, register-tiled, 16 warps) -------------------
// Optionally zero-fills zbuf rows (fused agg init).
__global__ __launch_bounds__(512) void gemm128_kernel(
    const float* __restrict__ A, const float* __restrict__ W,
    const float* __restrict__ bias, float* __restrict__ C,
    float* __restrict__ zbuf, int n, int act)
{
    extern __shared__ float s[];
    float* ws = s;                  // 128*128
    float* as = s + 128 * 128;      // 128*132
    int tid = threadIdx.x, wid = tid >> 5, lane = tid & 31;

    for (int i = tid * 4; i < 128 * 128; i += 512 * 4)
        *(float4*)&ws[i] = *(const float4*)&W[i];
    float4 bb = make_float4(0.f, 0.f, 0.f, 0.f);
    if (bias) bb = *(const float4*)&bias[lane * 4];
    __syncthreads();

    for (int rb = blockIdx.x * 128; rb < n; rb += gridDim.x * 128) {
        for (int i = tid; i < 128 * 32; i += 512) {
            int r = i >> 5, c4 = i & 31;
            float4 v = make_float4(0.f, 0.f, 0.f, 0.f);
            if (rb + r < n) v = *(const float4*)&A[(size_t)(rb + r) * HID + c4 * 4];
            *(float4*)&as[r * 132 + c4 * 4] = v;
        }
        __syncthreads();

        float acc[8][4];
        #pragma unroll
        for (int j = 0; j < 8; j++) {
            acc[j][0] = bb.x; acc[j][1] = bb.y; acc[j][2] = bb.z; acc[j][3] = bb.w;
        }
        const float* ar = &as[wid * 8 * 132];
        #pragma unroll 4
        for (int k = 0; k < 128; k++) {
            float4 wv = *(const float4*)&ws[k * 128 + lane * 4];
            #pragma unroll
            for (int j = 0; j < 8; j++) {
                float av = ar[j * 132 + k];
                acc[j][0] = fmaf(av, wv.x, acc[j][0]);
                acc[j][1] = fmaf(av, wv.y, acc[j][1]);
                acc[j][2] = fmaf(av, wv.z, acc[j][2]);
                acc[j][3] = fmaf(av, wv.w, acc[j][3]);
            }
        }
        #pragma unroll
        for (int j = 0; j < 8; j++) {
            int r = rb + wid * 8 + j;
            if (r < n) {
                float4 o;
                o.x = acc[j][0]; o.y = acc[j][1]; o.z = acc[j][2]; o.w = acc[j][3];
                if (act) { o.x = sspf(o.x); o.y = sspf(o.y); o.z = sspf(o.z); o.w = sspf(o.w); }
                *(float4*)&C[(size_t)r * HID + lane * 4] = o;
                if (zbuf)
                    *(float4*)&zbuf[(size_t)r * HID + lane * 4] =
                        make_float4(0.f, 0.f, 0.f, 0.f);
            }
        }
        __syncthreads();
    }
}

extern "C" void kernel_launch(void* const* d_in, const int* in_sizes, int n_in,
                              void* d_out, int out_size)
{
    const float* h      = (const float*)d_in[0];
    const float* pos    = (const float*)d_in[1];
    const int*   ei     = (const int*)d_in[2];
    const float* mlp_w1 = (const float*)d_in[3];
    const float* mlp_b1 = (const float*)d_in[4];
    const float* mlp_w2 = (const float*)d_in[5];
    const float* mlp_b2 = (const float*)d_in[6];
    const float* lin1_w = (const float*)d_in[7];
    const float* lin2_w = (const float*)d_in[8];
    const float* lin2_b = (const float*)d_in[9];
    const float* lin_w  = (const float*)d_in[10];
    const float* lin_b  = (const float*)d_in[11];
    float* out = (float*)d_out;

    int N = in_sizes[0] / HID;
    int E = in_sizes[2] / 2;

    float *xbuf, *aggbuf;
    cudaGetSymbolAddress((void**)&xbuf, g_x);
    cudaGetSymbolAddress((void**)&aggbuf, g_agg);

    const int GEMM_SMEM = (128 * 128 + 128 * 132) * (int)sizeof(float);
    const int EDGE_SMEM = E_SMEM_WORDS * (int)sizeof(float);
    cudaFuncSetAttribute(gemm128_kernel, cudaFuncAttributeMaxDynamicSharedMemorySize, GEMM_SMEM);
    cudaFuncSetAttribute(edge_mma_kernel, cudaFuncAttributeMaxDynamicSharedMemorySize, EDGE_SMEM);

    const int GRID = 148;

    // x = h @ lin1_w  (also zero-fills agg)
    gemm128_kernel<<<GRID, 512, GEMM_SMEM>>>(h, lin1_w, nullptr, xbuf, aggbuf, N, 0);
    edge_mma_kernel<<<GRID, 512, EDGE_SMEM>>>(pos, ei, mlp_w1, mlp_b1, mlp_w2, mlp_b2,
                                              xbuf, aggbuf, E);
    gemm128_kernel<<<GRID, 512, GEMM_SMEM>>>(aggbuf, lin2_w, lin2_b, xbuf, nullptr, N, 1);
    gemm128_kernel<<<GRID, 512, GEMM_SMEM>>>(xbuf, lin_w, lin_b, out, nullptr, N, 0);
}

// round 14
// speedup vs baseline: 1.0330x; 1.0330x over previous
#include <cuda_runtime.h>
#include <cstdint>
#include <math.h>

#define N_NODES_MAX 100000
#define HID 128
#define NF 128
#define NG 50

__device__ float g_x[(size_t)N_NODES_MAX * HID];
__device__ float g_agg[(size_t)N_NODES_MAX * HID];

__device__ __forceinline__ float sspf(float v) {
    float sp = (v > 20.0f) ? v : __logf(1.0f + __expf(v));
    return sp - 0.69314718056f;
}

__device__ __forceinline__ uint32_t f2tf(float f) {
    uint32_t u;
    asm("cvt.rna.tf32.f32 %0, %1;" : "=r"(u) : "f"(f));
    return u;
}

// D += A@B, m16n8k8 tf32, fp32 accumulate (baseline PTX)
__device__ __forceinline__ void mma8(float* c, const uint32_t* a, const uint32_t* b) {
    asm volatile(
        "mma.sync.aligned.m16n8k8.row.col.f32.tf32.tf32.f32 "
        "{%0,%1,%2,%3}, {%4,%5,%6,%7}, {%8,%9}, {%0,%1,%2,%3};"
        : "+f"(c[0]), "+f"(c[1]), "+f"(c[2]), "+f"(c[3])
        : "r"(a[0]), "r"(a[1]), "r"(a[2]), "r"(a[3]), "r"(b[0]), "r"(b[1]));
}

__device__ __forceinline__ void red4(float* p, float a, float b, float c, float d) {
    asm volatile("red.global.add.v4.f32 [%0], {%1, %2, %3, %4};"
                 :: "l"(p), "f"(a), "f"(b), "f"(c), "f"(d) : "memory");
}

// ------------------- Edge MLP (tf32 mma.sync, 8 warps x 16 filters) -------------------
// Tile = 128 edges. attr/hid stored PERMUTED as tf32 bits:
//   word offset of col c in its row = (c&3)*TCI + 2*(c>>3) + ((c>>2)&1)
// so cols (k, k+4) sit in adjacent words -> one LDS.64 per fragment pair.
// Bank check (16-lane phases, lanes 0-15: gi 0..3, ci 0..3; lanes 16-31: gi 4..7):
//   ASTR=72 (mod 32 = 8): {8*gi mod 32} = {0,8,16,24};  ATCI=14: {14*ci mod 32} = {0,14,28,10}
//     sums cover all 16 even residues -> conflict-free 8B pairs.
//   HSTR=136 (mod 32 = 8); HTCI=34: {34*ci mod 32} = {0,2,4,6} -> sums = all 16 evens. OK.
#define ASTR 72
#define ATCI 14
#define HSTR 136
#define HTCI 34

#define EO_ATTR 0
#define EO_HID  (128 * ASTR)                 // 9216
#define EO_ROWS (EO_HID + 128 * HSTR)        // 26624
#define EO_COLS (EO_ROWS + 128)
#define EO_CW   (EO_COLS + 128)
#define EO_D    (EO_CW + 128)
#define EO_B1   (EO_D + 128)
#define EO_B2   (EO_B1 + 128)
#define E_SMEM_WORDS (EO_B2 + 128)           // 27392 words = 109568 B

__global__ __launch_bounds__(256, 1) void edge_mma_kernel(
    const float* __restrict__ pos, const int* __restrict__ ei,
    const float* __restrict__ w1, const float* __restrict__ b1,
    const float* __restrict__ w2, const float* __restrict__ b2,
    const float* __restrict__ x, float* __restrict__ agg, int E)
{
    extern __shared__ float s[];
    uint32_t* attrP = (uint32_t*)(s + EO_ATTR);
    uint32_t* hidP  = (uint32_t*)(s + EO_HID);
    int*   rowsS = (int*)(s + EO_ROWS);
    int*   colsS = (int*)(s + EO_COLS);
    float* cwS   = s + EO_CW;
    float* dS    = s + EO_D;
    float* b1sS  = s + EO_B1;
    float* b2sS  = s + EO_B2;

    const int tid = threadIdx.x;
    const int wid = tid >> 5, lane = tid & 31;
    const int gi = lane >> 2, ci = lane & 3;
    const int nbase = wid * 16;

    // Persistent B fragments (tf32) in registers.
    uint32_t b1u[7][2][2], b2u[16][2][2];
    #pragma unroll
    for (int kt = 0; kt < 7; kt++)
        #pragma unroll
        for (int nt = 0; nt < 2; nt++) {
            int n = nbase + nt * 8 + gi;
            int k0 = kt * 8 + ci;
            b1u[kt][nt][0] = f2tf((k0 < NG) ? w1[k0 * 128 + n] : 0.f);
            b1u[kt][nt][1] = f2tf((k0 + 4 < NG) ? w1[(k0 + 4) * 128 + n] : 0.f);
        }
    #pragma unroll
    for (int kt = 0; kt < 16; kt++)
        #pragma unroll
        for (int nt = 0; nt < 2; nt++) {
            int n = nbase + nt * 8 + gi;
            int k0 = kt * 8 + ci;
            b2u[kt][nt][0] = f2tf(w2[k0 * 128 + n]);
            b2u[kt][nt][1] = f2tf(w2[(k0 + 4) * 128 + n]);
        }
    if (tid < 128) { b1sS[tid] = b1[tid]; b2sS[tid] = b2[tid]; }
    __syncthreads();

    float b1v[2][2], b2v[2][2];
    #pragma unroll
    for (int nt = 0; nt < 2; nt++) {
        int n0 = nbase + nt * 8 + 2 * ci;
        b1v[nt][0] = b1sS[n0]; b1v[nt][1] = b1sS[n0 + 1];
        b2v[nt][0] = b2sS[n0]; b2v[nt][1] = b2sS[n0 + 1];
    }

    const float step  = 10.0f / 49.0f;
    const float coeff = -0.5f / (step * step);

    for (int base = blockIdx.x * 128; base < E; base += gridDim.x * 128) {
        // ---- per-edge geometry ----
        if (tid < 128) {
            int e = base + tid;
            if (e < E) {
                int r = ei[e], c = ei[E + e];
                rowsS[tid] = r; colsS[tid] = c;
                float dx = pos[3 * r + 0] - pos[3 * c + 0];
                float dy = pos[3 * r + 1] - pos[3 * c + 1];
                float dz = pos[3 * r + 2] - pos[3 * c + 2];
                float d = sqrtf(dx * dx + dy * dy + dz * dz);
                dS[tid] = d;
                cwS[tid] = 0.5f * (__cosf(d * 0.314159265358979f) + 1.0f);
            } else {
                rowsS[tid] = 0; colsS[tid] = 0; dS[tid] = 0.f; cwS[tid] = 0.f;
            }
        }
        __syncthreads();

        // ---- Gaussian smearing -> permuted tf32 attr (cols >= 50 zero) ----
        {
            int e = tid >> 1, half = tid & 1;
            float d = dS[e];
            #pragma unroll
            for (int j = 0; j < 28; j++) {
                int k = half * 28 + j;
                float diff = d - (float)k * step;
                float v = (k < NG) ? __expf(coeff * diff * diff) : 0.f;
                attrP[e * ASTR + (k & 3) * ATCI + 2 * (k >> 3) + ((k >> 2) & 1)] = f2tf(v);
            }
        }
        __syncthreads();

        float acc[8][2][4];
        #pragma unroll
        for (int mt = 0; mt < 8; mt++)
            #pragma unroll
            for (int nt = 0; nt < 2; nt++)
                #pragma unroll
                for (int q = 0; q < 4; q++) acc[mt][nt][q] = 0.f;

        // ---- Layer 1: [128,56] @ [56,16] per warp (LDS.64 fragment pairs) ----
        #pragma unroll
        for (int kt = 0; kt < 7; kt++) {
            #pragma unroll
            for (int mt = 0; mt < 8; mt++) {
                int r = mt * 16 + gi;
                uint2 lo = *(const uint2*)&attrP[r * ASTR + ci * ATCI + 2 * kt];
                uint2 hi = *(const uint2*)&attrP[(r + 8) * ASTR + ci * ATCI + 2 * kt];
                uint32_t a[4] = {lo.x, hi.x, lo.y, hi.y};
                mma8(acc[mt][0], a, b1u[kt][0]);
                mma8(acc[mt][1], a, b1u[kt][1]);
            }
        }

        // ---- bias + ssp -> permuted hid tf32 bits ----
        #pragma unroll
        for (int mt = 0; mt < 8; mt++) {
            int r = mt * 16 + gi;
            #pragma unroll
            for (int nt = 0; nt < 2; nt++) {
                int c0 = nbase + nt * 8 + 2 * ci;
                int c1 = c0 + 1;
                int o0 = (c0 & 3) * HTCI + 2 * (c0 >> 3) + ((c0 >> 2) & 1);
                int o1 = (c1 & 3) * HTCI + 2 * (c1 >> 3) + ((c1 >> 2) & 1);
                hidP[r * HSTR + o0]       = f2tf(sspf(acc[mt][nt][0] + b1v[nt][0]));
                hidP[r * HSTR + o1]       = f2tf(sspf(acc[mt][nt][1] + b1v[nt][1]));
                hidP[(r + 8) * HSTR + o0] = f2tf(sspf(acc[mt][nt][2] + b1v[nt][0]));
                hidP[(r + 8) * HSTR + o1] = f2tf(sspf(acc[mt][nt][3] + b1v[nt][1]));
            }
        }
        __syncthreads();

        #pragma unroll
        for (int mt = 0; mt < 8; mt++)
            #pragma unroll
            for (int nt = 0; nt < 2; nt++)
                #pragma unroll
                for (int q = 0; q < 4; q++) acc[mt][nt][q] = 0.f;

        // ---- Layer 2: [128,128] @ [128,16] per warp (LDS.64 fragment pairs) ----
        #pragma unroll
        for (int kt = 0; kt < 16; kt++) {
            #pragma unroll
            for (int mt = 0; mt < 8; mt++) {
                int r = mt * 16 + gi;
                uint2 lo = *(const uint2*)&hidP[r * HSTR + ci * HTCI + 2 * kt];
                uint2 hi = *(const uint2*)&hidP[(r + 8) * HSTR + ci * HTCI + 2 * kt];
                uint32_t a[4] = {lo.x, hi.x, lo.y, hi.y};
                mma8(acc[mt][0], a, b2u[kt][0]);
                mma8(acc[mt][1], a, b2u[kt][1]);
            }
        }

        // ---- epilogue: bias, cutoff, pair-shuffle -> float4 gather + red.v4 ----
        {
            const int odd = ci & 1;
            #pragma unroll
            for (int mt = 0; mt < 8; mt++) {
                int r0 = mt * 16 + gi, r1 = r0 + 8;
                float cw0 = cwS[r0], cw1 = cwS[r1];
                int mr = odd ? r1 : r0;
                int gr = rowsS[mr], gc = colsS[mr];
                #pragma unroll
                for (int nt = 0; nt < 2; nt++) {
                    float wa = (acc[mt][nt][0] + b2v[nt][0]) * cw0;
                    float wb = (acc[mt][nt][1] + b2v[nt][1]) * cw0;
                    float wc = (acc[mt][nt][2] + b2v[nt][0]) * cw1;
                    float wd = (acc[mt][nt][3] + b2v[nt][1]) * cw1;
                    // lane pair (ci, ci^1): even keeps row r0, odd keeps row r1.
                    float sx = odd ? wa : wc;
                    float sy = odd ? wb : wd;
                    float rx = __shfl_xor_sync(0xffffffffu, sx, 1);
                    float ry = __shfl_xor_sync(0xffffffffu, sy, 1);
                    float v0 = odd ? rx : wa;
                    float v1 = odd ? ry : wb;
                    float v2 = odd ? wc : rx;
                    float v3 = odd ? wd : ry;
                    int cb = nbase + nt * 8 + 4 * (ci >> 1);
                    float4 xv = *(const float4*)&x[(size_t)gc * 128 + cb];
                    red4(&agg[(size_t)gr * 128 + cb],
                         v0 * xv.x, v1 * xv.y, v2 * xv.z, v3 * xv.w);
                }
            }
        }
        __syncthreads();
    }
}

// ------------------- Node GEMM (fp32, register-tiled, 16 warps) -------------------
// Optionally zero-fills zbuf rows (fused agg init).
__global__ __launch_bounds__(512) void gemm128_kernel(
    const float* __restrict__ A, const float* __restrict__ W,
    const float* __restrict__ bias, float* __restrict__ C,
    float* __restrict__ zbuf, int n, int act)
{
    extern __shared__ float s[];
    float* ws = s;                  // 128*128
    float* as = s + 128 * 128;      // 128*132
    int tid = threadIdx.x, wid = tid >> 5, lane = tid & 31;

    for (int i = tid * 4; i < 128 * 128; i += 512 * 4)
        *(float4*)&ws[i] = *(const float4*)&W[i];
    float4 bb = make_float4(0.f, 0.f, 0.f, 0.f);
    if (bias) bb = *(const float4*)&bias[lane * 4];
    __syncthreads();

    for (int rb = blockIdx.x * 128; rb < n; rb += gridDim.x * 128) {
        for (int i = tid; i < 128 * 32; i += 512) {
            int r = i >> 5, c4 = i & 31;
            float4 v = make_float4(0.f, 0.f, 0.f, 0.f);
            if (rb + r < n) v = *(const float4*)&A[(size_t)(rb + r) * HID + c4 * 4];
            *(float4*)&as[r * 132 + c4 * 4] = v;
        }
        __syncthreads();

        float acc[8][4];
        #pragma unroll
        for (int j = 0; j < 8; j++) {
            acc[j][0] = bb.x; acc[j][1] = bb.y; acc[j][2] = bb.z; acc[j][3] = bb.w;
        }
        const float* ar = &as[wid * 8 * 132];
        #pragma unroll 4
        for (int k = 0; k < 128; k++) {
            float4 wv = *(const float4*)&ws[k * 128 + lane * 4];
            #pragma unroll
            for (int j = 0; j < 8; j++) {
                float av = ar[j * 132 + k];
                acc[j][0] = fmaf(av, wv.x, acc[j][0]);
                acc[j][1] = fmaf(av, wv.y, acc[j][1]);
                acc[j][2] = fmaf(av, wv.z, acc[j][2]);
                acc[j][3] = fmaf(av, wv.w, acc[j][3]);
            }
        }
        #pragma unroll
        for (int j = 0; j < 8; j++) {
            int r = rb + wid * 8 + j;
            if (r < n) {
                float4 o;
                o.x = acc[j][0]; o.y = acc[j][1]; o.z = acc[j][2]; o.w = acc[j][3];
                if (act) { o.x = sspf(o.x); o.y = sspf(o.y); o.z = sspf(o.z); o.w = sspf(o.w); }
                *(float4*)&C[(size_t)r * HID + lane * 4] = o;
                if (zbuf)
                    *(float4*)&zbuf[(size_t)r * HID + lane * 4] =
                        make_float4(0.f, 0.f, 0.f, 0.f);
            }
        }
        __syncthreads();
    }
}

extern "C" void kernel_launch(void* const* d_in, const int* in_sizes, int n_in,
                              void* d_out, int out_size)
{
    const float* h      = (const float*)d_in[0];
    const float* pos    = (const float*)d_in[1];
    const int*   ei     = (const int*)d_in[2];
    const float* mlp_w1 = (const float*)d_in[3];
    const float* mlp_b1 = (const float*)d_in[4];
    const float* mlp_w2 = (const float*)d_in[5];
    const float* mlp_b2 = (const float*)d_in[6];
    const float* lin1_w = (const float*)d_in[7];
    const float* lin2_w = (const float*)d_in[8];
    const float* lin2_b = (const float*)d_in[9];
    const float* lin_w  = (const float*)d_in[10];
    const float* lin_b  = (const float*)d_in[11];
    float* out = (float*)d_out;

    int N = in_sizes[0] / HID;
    int E = in_sizes[2] / 2;

    float *xbuf, *aggbuf;
    cudaGetSymbolAddress((void**)&xbuf, g_x);
    cudaGetSymbolAddress((void**)&aggbuf, g_agg);

    const int GEMM_SMEM = (128 * 128 + 128 * 132) * (int)sizeof(float);
    const int EDGE_SMEM = E_SMEM_WORDS * (int)sizeof(float);
    cudaFuncSetAttribute(gemm128_kernel, cudaFuncAttributeMaxDynamicSharedMemorySize, GEMM_SMEM);
    cudaFuncSetAttribute(edge_mma_kernel, cudaFuncAttributeMaxDynamicSharedMemorySize, EDGE_SMEM);

    const int GRID = 148;

    // x = h @ lin1_w  (also zero-fills agg)
    gemm128_kernel<<<GRID, 512, GEMM_SMEM>>>(h, lin1_w, nullptr, xbuf, aggbuf, N, 0);
    edge_mma_kernel<<<GRID, 256, EDGE_SMEM>>>(pos, ei, mlp_w1, mlp_b1, mlp_w2, mlp_b2,
                                              xbuf, aggbuf, E);
    gemm128_kernel<<<GRID, 512, GEMM_SMEM>>>(aggbuf, lin2_w, lin2_b, xbuf, nullptr, N, 1);
    gemm128_kernel<<<GRID, 512, GEMM_SMEM>>>(xbuf, lin_w, lin_b, out, nullptr, N, 0);
}

// round 15
// speedup vs baseline: 1.2184x; 1.1795x over previous
#include <cuda_runtime.h>
#include <cuda_fp16.h>
#include <cstdint>
#include <math.h>

#define N_NODES_MAX 100000
#define HID 128
#define NF 128
#define NG 50

__device__ float g_x[(size_t)N_NODES_MAX * HID];
__device__ float g_agg[(size_t)N_NODES_MAX * HID];

__device__ __forceinline__ float sspf(float v) {
    float sp = (v > 20.0f) ? v : __logf(1.0f + __expf(v));
    return sp - 0.69314718056f;
}

__device__ __forceinline__ uint32_t h2u(__half2 h) {
    uint32_t u; memcpy(&u, &h, 4); return u;
}

// D += A@B, m16n8k16 fp16 inputs, fp32 accumulate (baseline PTX, sm_80+)
__device__ __forceinline__ void mma16(float* c, const uint32_t* a, const uint32_t* b) {
    asm volatile(
        "mma.sync.aligned.m16n8k16.row.col.f32.f16.f16.f32 "
        "{%0,%1,%2,%3}, {%4,%5,%6,%7}, {%8,%9}, {%0,%1,%2,%3};"
        : "+f"(c[0]), "+f"(c[1]), "+f"(c[2]), "+f"(c[3])
        : "r"(a[0]), "r"(a[1]), "r"(a[2]), "r"(a[3]), "r"(b[0]), "r"(b[1]));
}

__device__ __forceinline__ void red4(float* p, float a, float b, float c, float d) {
    asm volatile("red.global.add.v4.f32 [%0], {%1, %2, %3, %4};"
                 :: "l"(p), "f"(a), "f"(b), "f"(c), "f"(d) : "memory");
}

// ------------------- Edge MLP (fp16 mma.sync, 8 warps x 16 filters) -------------------
// Tile = 128 edges. attr/hid stored as half2 words, scalar-layout rows.
// Bank check (full-warp single phase, 32 lanes: gi 0..7, ci 0..3):
//   word = r*STR + kt*8 + ci (+4), r = mt*16 + gi.
//   AS2=36 (mod 32 = 4): {4*gi} = {0,4,..,28}; +ci 0..3 -> all 32 banks distinct.
//   HS2=68 (mod 32 = 4): same. Stores (word = r*HS2 + const + nt*4 + ci): same. OK.
#define AS2 36    // attr row stride in half2 words (64 cols = 32 words + 4 pad)
#define HS2 68    // hid row stride in half2 words (128 cols = 64 words + 4 pad)

#define EO_ATTR 0
#define EO_HID  (128 * AS2)                  // 4608
#define EO_ROWS (EO_HID + 128 * HS2)         // 13312
#define EO_COLS (EO_ROWS + 128)
#define EO_CW   (EO_COLS + 128)
#define EO_D    (EO_CW + 128)
#define EO_B1   (EO_D + 128)
#define EO_B2   (EO_B1 + 128)
#define E_SMEM_WORDS (EO_B2 + 128)           // 14080 words = 56320 B

__global__ __launch_bounds__(256, 1) void edge_mma_kernel(
    const float* __restrict__ pos, const int* __restrict__ ei,
    const float* __restrict__ w1, const float* __restrict__ b1,
    const float* __restrict__ w2, const float* __restrict__ b2,
    const float* __restrict__ x, float* __restrict__ agg, int E)
{
    extern __shared__ float s[];
    uint32_t* attr2 = (uint32_t*)(s + EO_ATTR);   // half2 words
    uint32_t* hid2  = (uint32_t*)(s + EO_HID);    // half2 words
    int*   rowsS = (int*)(s + EO_ROWS);
    int*   colsS = (int*)(s + EO_COLS);
    float* cwS   = s + EO_CW;
    float* dS    = s + EO_D;
    float* b1sS  = s + EO_B1;
    float* b2sS  = s + EO_B2;

    const int tid = threadIdx.x;
    const int wid = tid >> 5, lane = tid & 31;
    const int gi = lane >> 2, ci = lane & 3;
    const int nbase = wid * 16;

    // Persistent B fragments (fp16) in registers.
    // m16n8k16 B frag: b0 = halves {k0, k0+1}, b1 = {k0+8, k0+9}, k0 = kt*16 + 2*ci, n = gi-col.
    uint32_t b1u[4][2][2], b2u[8][2][2];
    #pragma unroll
    for (int kt = 0; kt < 4; kt++)
        #pragma unroll
        for (int nt = 0; nt < 2; nt++) {
            int n = nbase + nt * 8 + gi;
            int k0 = kt * 16 + 2 * ci;
            float p0 = (k0     < NG) ? w1[(k0    ) * 128 + n] : 0.f;
            float p1 = (k0 + 1 < NG) ? w1[(k0 + 1) * 128 + n] : 0.f;
            float p2 = (k0 + 8 < NG) ? w1[(k0 + 8) * 128 + n] : 0.f;
            float p3 = (k0 + 9 < NG) ? w1[(k0 + 9) * 128 + n] : 0.f;
            b1u[kt][nt][0] = h2u(__floats2half2_rn(p0, p1));
            b1u[kt][nt][1] = h2u(__floats2half2_rn(p2, p3));
        }
    #pragma unroll
    for (int kt = 0; kt < 8; kt++)
        #pragma unroll
        for (int nt = 0; nt < 2; nt++) {
            int n = nbase + nt * 8 + gi;
            int k0 = kt * 16 + 2 * ci;
            b2u[kt][nt][0] = h2u(__floats2half2_rn(w2[(k0    ) * 128 + n],
                                                   w2[(k0 + 1) * 128 + n]));
            b2u[kt][nt][1] = h2u(__floats2half2_rn(w2[(k0 + 8) * 128 + n],
                                                   w2[(k0 + 9) * 128 + n]));
        }
    if (tid < 128) { b1sS[tid] = b1[tid]; b2sS[tid] = b2[tid]; }
    __syncthreads();

    float b1v[2][2], b2v[2][2];
    #pragma unroll
    for (int nt = 0; nt < 2; nt++) {
        int n0 = nbase + nt * 8 + 2 * ci;
        b1v[nt][0] = b1sS[n0]; b1v[nt][1] = b1sS[n0 + 1];
        b2v[nt][0] = b2sS[n0]; b2v[nt][1] = b2sS[n0 + 1];
    }

    const float step  = 10.0f / 49.0f;
    const float coeff = -0.5f / (step * step);

    for (int base = blockIdx.x * 128; base < E; base += gridDim.x * 128) {
        // ---- per-edge geometry ----
        if (tid < 128) {
            int e = base + tid;
            if (e < E) {
                int r = ei[e], c = ei[E + e];
                rowsS[tid] = r; colsS[tid] = c;
                float dx = pos[3 * r + 0] - pos[3 * c + 0];
                float dy = pos[3 * r + 1] - pos[3 * c + 1];
                float dz = pos[3 * r + 2] - pos[3 * c + 2];
                float d = sqrtf(dx * dx + dy * dy + dz * dz);
                dS[tid] = d;
                cwS[tid] = 0.5f * (__cosf(d * 0.314159265358979f) + 1.0f);
            } else {
                rowsS[tid] = 0; colsS[tid] = 0; dS[tid] = 0.f; cwS[tid] = 0.f;
            }
        }
        __syncthreads();

        // ---- Gaussian smearing -> half2 attr rows (64 cols, >=50 zero) ----
        {
            int e = tid >> 1, half = tid & 1;   // 2 threads/edge, 16 half2 words each
            float d = dS[e];
            #pragma unroll
            for (int j = 0; j < 16; j++) {
                int w = half * 16 + j;
                int k0 = 2 * w, k1 = 2 * w + 1;
                float f0 = d - (float)k0 * step;
                float f1 = d - (float)k1 * step;
                float v0 = (k0 < NG) ? __expf(coeff * f0 * f0) : 0.f;
                float v1 = (k1 < NG) ? __expf(coeff * f1 * f1) : 0.f;
                attr2[e * AS2 + w] = h2u(__floats2half2_rn(v0, v1));
            }
        }
        __syncthreads();

        float acc[8][2][4];
        #pragma unroll
        for (int mt = 0; mt < 8; mt++)
            #pragma unroll
            for (int nt = 0; nt < 2; nt++)
                #pragma unroll
                for (int q = 0; q < 4; q++) acc[mt][nt][q] = 0.f;

        // ---- Layer 1: [128,64] @ [64,16] per warp (4 k-chunks of 16) ----
        #pragma unroll
        for (int kt = 0; kt < 4; kt++) {
            #pragma unroll
            for (int mt = 0; mt < 8; mt++) {
                int r = mt * 16 + gi;
                uint32_t a[4];
                a[0] = attr2[r * AS2 + kt * 8 + ci];
                a[1] = attr2[(r + 8) * AS2 + kt * 8 + ci];
                a[2] = attr2[r * AS2 + kt * 8 + ci + 4];
                a[3] = attr2[(r + 8) * AS2 + kt * 8 + ci + 4];
                mma16(acc[mt][0], a, b1u[kt][0]);
                mma16(acc[mt][1], a, b1u[kt][1]);
            }
        }

        // ---- bias + ssp -> half2 hid rows ----
        #pragma unroll
        for (int mt = 0; mt < 8; mt++) {
            int r = mt * 16 + gi;
            #pragma unroll
            for (int nt = 0; nt < 2; nt++) {
                int wv = (nbase >> 1) + nt * 4 + ci;   // half2 word of col pair
                float s0 = sspf(acc[mt][nt][0] + b1v[nt][0]);
                float s1 = sspf(acc[mt][nt][1] + b1v[nt][1]);
                float s2 = sspf(acc[mt][nt][2] + b1v[nt][0]);
                float s3 = sspf(acc[mt][nt][3] + b1v[nt][1]);
                hid2[r * HS2 + wv]       = h2u(__floats2half2_rn(s0, s1));
                hid2[(r + 8) * HS2 + wv] = h2u(__floats2half2_rn(s2, s3));
            }
        }
        __syncthreads();

        #pragma unroll
        for (int mt = 0; mt < 8; mt++)
            #pragma unroll
            for (int nt = 0; nt < 2; nt++)
                #pragma unroll
                for (int q = 0; q < 4; q++) acc[mt][nt][q] = 0.f;

        // ---- Layer 2: [128,128] @ [128,16] per warp (8 k-chunks of 16) ----
        #pragma unroll
        for (int kt = 0; kt < 8; kt++) {
            #pragma unroll
            for (int mt = 0; mt < 8; mt++) {
                int r = mt * 16 + gi;
                uint32_t a[4];
                a[0] = hid2[r * HS2 + kt * 8 + ci];
                a[1] = hid2[(r + 8) * HS2 + kt * 8 + ci];
                a[2] = hid2[r * HS2 + kt * 8 + ci + 4];
                a[3] = hid2[(r + 8) * HS2 + kt * 8 + ci + 4];
                mma16(acc[mt][0], a, b2u[kt][0]);
                mma16(acc[mt][1], a, b2u[kt][1]);
            }
        }

        // ---- epilogue: bias, cutoff, pair-shuffle -> float4 gather + red.v4 ----
        {
            const int odd = ci & 1;
            #pragma unroll
            for (int mt = 0; mt < 8; mt++) {
                int r0 = mt * 16 + gi, r1 = r0 + 8;
                float cw0 = cwS[r0], cw1 = cwS[r1];
                int mr = odd ? r1 : r0;
                int gr = rowsS[mr], gc = colsS[mr];
                #pragma unroll
                for (int nt = 0; nt < 2; nt++) {
                    float wa = (acc[mt][nt][0] + b2v[nt][0]) * cw0;
                    float wb = (acc[mt][nt][1] + b2v[nt][1]) * cw0;
                    float wc = (acc[mt][nt][2] + b2v[nt][0]) * cw1;
                    float wd = (acc[mt][nt][3] + b2v[nt][1]) * cw1;
                    // lane pair (ci, ci^1): even keeps row r0, odd keeps row r1.
                    float sx = odd ? wa : wc;
                    float sy = odd ? wb : wd;
                    float rx = __shfl_xor_sync(0xffffffffu, sx, 1);
                    float ry = __shfl_xor_sync(0xffffffffu, sy, 1);
                    float v0 = odd ? rx : wa;
                    float v1 = odd ? ry : wb;
                    float v2 = odd ? wc : rx;
                    float v3 = odd ? wd : ry;
                    int cb = nbase + nt * 8 + 4 * (ci >> 1);
                    float4 xv = *(const float4*)&x[(size_t)gc * 128 + cb];
                    red4(&agg[(size_t)gr * 128 + cb],
                         v0 * xv.x, v1 * xv.y, v2 * xv.z, v3 * xv.w);
                }
            }
        }
        __syncthreads();
    }
}

// ------------------- Node GEMM (fp32, register-tiled, 16 warps) -------------------
// Optionally zero-fills zbuf rows (fused agg init).
__global__ __launch_bounds__(512) void gemm128_kernel(
    const float* __restrict__ A, const float* __restrict__ W,
    const float* __restrict__ bias, float* __restrict__ C,
    float* __restrict__ zbuf, int n, int act)
{
    extern __shared__ float s[];
    float* ws = s;                  // 128*128
    float* as = s + 128 * 128;      // 128*132
    int tid = threadIdx.x, wid = tid >> 5, lane = tid & 31;

    for (int i = tid * 4; i < 128 * 128; i += 512 * 4)
        *(float4*)&ws[i] = *(const float4*)&W[i];
    float4 bb = make_float4(0.f, 0.f, 0.f, 0.f);
    if (bias) bb = *(const float4*)&bias[lane * 4];
    __syncthreads();

    for (int rb = blockIdx.x * 128; rb < n; rb += gridDim.x * 128) {
        for (int i = tid; i < 128 * 32; i += 512) {
            int r = i >> 5, c4 = i & 31;
            float4 v = make_float4(0.f, 0.f, 0.f, 0.f);
            if (rb + r < n) v = *(const float4*)&A[(size_t)(rb + r) * HID + c4 * 4];
            *(float4*)&as[r * 132 + c4 * 4] = v;
        }
        __syncthreads();

        float acc[8][4];
        #pragma unroll
        for (int j = 0; j < 8; j++) {
            acc[j][0] = bb.x; acc[j][1] = bb.y; acc[j][2] = bb.z; acc[j][3] = bb.w;
        }
        const float* ar = &as[wid * 8 * 132];
        #pragma unroll 4
        for (int k = 0; k < 128; k++) {
            float4 wv = *(const float4*)&ws[k * 128 + lane * 4];
            #pragma unroll
            for (int j = 0; j < 8; j++) {
                float av = ar[j * 132 + k];
                acc[j][0] = fmaf(av, wv.x, acc[j][0]);
                acc[j][1] = fmaf(av, wv.y, acc[j][1]);
                acc[j][2] = fmaf(av, wv.z, acc[j][2]);
                acc[j][3] = fmaf(av, wv.w, acc[j][3]);
            }
        }
        #pragma unroll
        for (int j = 0; j < 8; j++) {
            int r = rb + wid * 8 + j;
            if (r < n) {
                float4 o;
                o.x = acc[j][0]; o.y = acc[j][1]; o.z = acc[j][2]; o.w = acc[j][3];
                if (act) { o.x = sspf(o.x); o.y = sspf(o.y); o.z = sspf(o.z); o.w = sspf(o.w); }
                *(float4*)&C[(size_t)r * HID + lane * 4] = o;
                if (zbuf)
                    *(float4*)&zbuf[(size_t)r * HID + lane * 4] =
                        make_float4(0.f, 0.f, 0.f, 0.f);
            }
        }
        __syncthreads();
    }
}

extern "C" void kernel_launch(void* const* d_in, const int* in_sizes, int n_in,
                              void* d_out, int out_size)
{
    const float* h      = (const float*)d_in[0];
    const float* pos    = (const float*)d_in[1];
    const int*   ei     = (const int*)d_in[2];
    const float* mlp_w1 = (const float*)d_in[3];
    const float* mlp_b1 = (const float*)d_in[4];
    const float* mlp_w2 = (const float*)d_in[5];
    const float* mlp_b2 = (const float*)d_in[6];
    const float* lin1_w = (const float*)d_in[7];
    const float* lin2_w = (const float*)d_in[8];
    const float* lin2_b = (const float*)d_in[9];
    const float* lin_w  = (const float*)d_in[10];
    const float* lin_b  = (const float*)d_in[11];
    float* out = (float*)d_out;

    int N = in_sizes[0] / HID;
    int E = in_sizes[2] / 2;

    float *xbuf, *aggbuf;
    cudaGetSymbolAddress((void**)&xbuf, g_x);
    cudaGetSymbolAddress((void**)&aggbuf, g_agg);

    const int GEMM_SMEM = (128 * 128 + 128 * 132) * (int)sizeof(float);
    const int EDGE_SMEM = E_SMEM_WORDS * (int)sizeof(float);
    cudaFuncSetAttribute(gemm128_kernel, cudaFuncAttributeMaxDynamicSharedMemorySize, GEMM_SMEM);
    cudaFuncSetAttribute(edge_mma_kernel, cudaFuncAttributeMaxDynamicSharedMemorySize, EDGE_SMEM);

    const int GRID = 148;

    // x = h @ lin1_w  (also zero-fills agg)
    gemm128_kernel<<<GRID, 512, GEMM_SMEM>>>(h, lin1_w, nullptr, xbuf, aggbuf, N, 0);
    edge_mma_kernel<<<GRID, 256, EDGE_SMEM>>>(pos, ei, mlp_w1, mlp_b1, mlp_w2, mlp_b2,
                                              xbuf, aggbuf, E);
    gemm128_kernel<<<GRID, 512, GEMM_SMEM>>>(aggbuf, lin2_w, lin2_b, xbuf, nullptr, N, 1);
    gemm128_kernel<<<GRID, 512, GEMM_SMEM>>>(xbuf, lin_w, lin_b, out, nullptr, N, 0);
}